// round 10
// baseline (speedup 1.0000x reference)
#include <cuda_runtime.h>

// Problem constants (fixed by the dataset)
#define BB 4
#define NN 40960
#define KK 16
#define DOUT 16
#define BN_EPS 1e-5f

// Scratch: xyz padded to float4 so each neighbor gather is a single LDG.128.
// B*N = 163840 float4 = 2.62 MB. __device__ global => allocation-free.
__device__ float4 g_xyz4[BB * NN];

// --- Kernel 1: pack xyz [B,N,3] f32 -> float4 scratch, 4 points/thread ----
__global__ void pack_xyz_kernel(const float4* __restrict__ xyz4) {
    int i = blockIdx.x * blockDim.x + threadIdx.x;   // 0 .. B*N/4-1
    if (i < BB * NN / 4) {
        float4 a = xyz4[3 * i + 0];   // x0 y0 z0 x1
        float4 b = xyz4[3 * i + 1];   // y1 z1 x2 y2
        float4 c = xyz4[3 * i + 2];   // z2 x3 y3 z3
        float4* o = g_xyz4 + 4 * i;
        o[0] = make_float4(a.x, a.y, a.z, 0.0f);
        o[1] = make_float4(a.w, b.x, b.y, 0.0f);
        o[2] = make_float4(b.z, b.w, c.x, 0.0f);
        o[3] = make_float4(c.y, c.z, c.w, 0.0f);
    }
}

// --- Kernel 2: fused gather + encode + conv1x1 + BN + ReLU ---------------
// Thread = (b, n, 8 consecutive k). 8 front-batched random gathers/thread;
// shared tile/pointers keep regs ~75-80. Cap at 3 CTAs/SM (85 regs):
// 24 warps x 8 = 192 outstanding gathers/SM (R8 was 32x4=128, R9 16x8=128).
__global__ __launch_bounds__(256, 3) void lse_kernel(
    const int* __restrict__ idx,         // [B,N,K] int32
    const float* __restrict__ W,         // [DOUT,10]
    const float* __restrict__ gamma,
    const float* __restrict__ beta,
    const float* __restrict__ rmean,
    const float* __restrict__ rvar,
    float* __restrict__ out)             // [B,DOUT,N,K]
{
    // Per-block prepped weights: y[o] = bias + w0*dist + A.tile + Bm.neigh
    __shared__ float sW0[DOUT];
    __shared__ float sA[DOUT][3];
    __shared__ float sBm[DOUT][3];
    __shared__ float sBias[DOUT];

    int t = threadIdx.x;
    if (t < DOUT) {
        float inv_std = rsqrtf(rvar[t] + BN_EPS);
        float sc = gamma[t] * inv_std;
        const float* w = W + t * 10;
        sW0[t] = w[0] * sc;
#pragma unroll
        for (int c = 0; c < 3; c++) {
            float wr = w[1 + c], wt = w[4 + c], wn = w[7 + c];
            sA[t][c]  = (wr + wt) * sc;   // coefficient of tile (center xyz)
            sBm[t][c] = (wn - wr) * sc;   // coefficient of neighbor xyz
        }
        sBias[t] = beta[t] - gamma[t] * rmean[t] * inv_std;
    }
    __syncthreads();

    // gid in [0, B*N*2): thread covers k [k0, k0+8), k0 = (r&1)*8
    int gid = blockIdx.x * blockDim.x + t;
    int b = gid / (NN * 2);
    int r = gid - b * (NN * 2);
    int n = r >> 1;
    int k0 = (r & 1) << 3;                           // 0 or 8

    // ---- batched loads: 2 idx int4 (32B adjacent) + tile + 8 gathers ----
    const int* ip = idx + (b * NN + n) * KK + k0;
    const int4 iv0 = *(const int4*)(ip);
    const int4 iv1 = *(const int4*)(ip + 4);

    const float4* xb = g_xyz4 + b * NN;
    float4 tile = xb[n];

    float4 g0 = xb[iv0.x];
    float4 g1 = xb[iv0.y];
    float4 g2 = xb[iv0.z];
    float4 g3 = xb[iv0.w];
    float4 g4 = xb[iv1.x];
    float4 g5 = xb[iv1.y];
    float4 g6 = xb[iv1.z];
    float4 g7 = xb[iv1.w];

    // ---- distances ----
    float dx, dy, dz;
    dx = tile.x - g0.x; dy = tile.y - g0.y; dz = tile.z - g0.z;
    float d0 = sqrtf(dx * dx + dy * dy + dz * dz);
    dx = tile.x - g1.x; dy = tile.y - g1.y; dz = tile.z - g1.z;
    float d1 = sqrtf(dx * dx + dy * dy + dz * dz);
    dx = tile.x - g2.x; dy = tile.y - g2.y; dz = tile.z - g2.z;
    float d2 = sqrtf(dx * dx + dy * dy + dz * dz);
    dx = tile.x - g3.x; dy = tile.y - g3.y; dz = tile.z - g3.z;
    float d3 = sqrtf(dx * dx + dy * dy + dz * dz);
    dx = tile.x - g4.x; dy = tile.y - g4.y; dz = tile.z - g4.z;
    float d4 = sqrtf(dx * dx + dy * dy + dz * dz);
    dx = tile.x - g5.x; dy = tile.y - g5.y; dz = tile.z - g5.z;
    float d5 = sqrtf(dx * dx + dy * dy + dz * dz);
    dx = tile.x - g6.x; dy = tile.y - g6.y; dz = tile.z - g6.z;
    float d6 = sqrtf(dx * dx + dy * dy + dz * dz);
    dx = tile.x - g7.x; dy = tile.y - g7.y; dz = tile.z - g7.z;
    float d7 = sqrtf(dx * dx + dy * dy + dz * dz);

    // out[((b*16+o)*N + n)*K + k0]; per-o: two adjacent float4 (32B)
    float* op = out + (b * DOUT * NN + n) * KK + k0;

#pragma unroll
    for (int o = 0; o < DOUT; o++) {
        float w0 = sW0[o];
        float q0 = sA[o][0], q1 = sA[o][1], q2 = sA[o][2];
        float m0 = sBm[o][0], m1 = sBm[o][1], m2 = sBm[o][2];
        // tile term shared by all 8 k of this thread
        float tt = sBias[o] + q0 * tile.x + q1 * tile.y + q2 * tile.z;

        float y0 = tt + w0 * d0 + m0 * g0.x + m1 * g0.y + m2 * g0.z;
        float y1 = tt + w0 * d1 + m0 * g1.x + m1 * g1.y + m2 * g1.z;
        float y2 = tt + w0 * d2 + m0 * g2.x + m1 * g2.y + m2 * g2.z;
        float y3 = tt + w0 * d3 + m0 * g3.x + m1 * g3.y + m2 * g3.z;
        float y4 = tt + w0 * d4 + m0 * g4.x + m1 * g4.y + m2 * g4.z;
        float y5 = tt + w0 * d5 + m0 * g5.x + m1 * g5.y + m2 * g5.z;
        float y6 = tt + w0 * d6 + m0 * g6.x + m1 * g6.y + m2 * g6.z;
        float y7 = tt + w0 * d7 + m0 * g7.x + m1 * g7.y + m2 * g7.z;

        float* po = op + o * (NN * KK);
        *(float4*)(po)     = make_float4(fmaxf(y0, 0.0f), fmaxf(y1, 0.0f),
                                         fmaxf(y2, 0.0f), fmaxf(y3, 0.0f));
        *(float4*)(po + 4) = make_float4(fmaxf(y4, 0.0f), fmaxf(y5, 0.0f),
                                         fmaxf(y6, 0.0f), fmaxf(y7, 0.0f));
    }
}

extern "C" void kernel_launch(void* const* d_in, const int* in_sizes, int n_in,
                              void* d_out, int out_size) {
    // Bind inputs by element count (robust to metadata ordering).
    const float* xyz = 0;
    const int*   idx = 0;
    const float* W   = 0;
    const float* p16[4] = {0, 0, 0, 0};   // gamma, beta, rmean, rvar in order
    int n16 = 0;

    for (int i = 0; i < n_in; i++) {
        switch (in_sizes[i]) {
            case BB * NN * 3:        xyz = (const float*)d_in[i]; break;   // 491520
            case BB * NN * KK:       idx = (const int*)d_in[i];   break;   // 2621440
            case DOUT * 10:          W   = (const float*)d_in[i]; break;   // 160
            case DOUT:               if (n16 < 4) p16[n16++] = (const float*)d_in[i]; break;
            default: break;           // feature (1310720): unused
        }
    }
    const float* gamma = p16[0];
    const float* beta  = p16[1];
    const float* rmean = p16[2];
    const float* rvar  = p16[3];
    float* out = (float*)d_out;
    (void)out_size;

    const int pack_threads = BB * NN / 4;                 // 40960
    pack_xyz_kernel<<<(pack_threads + 255) / 256, 256>>>((const float4*)xyz);

    // One thread per (b, n, 8-k half): B*N*2 threads.
    const int total = BB * NN * 2;                        // 327680
    lse_kernel<<<total / 256, 256>>>(idx, W, gamma, beta, rmean, rvar, out);
}

// round 11
// speedup vs baseline: 1.3538x; 1.3538x over previous
#include <cuda_runtime.h>

// Problem constants (fixed by the dataset)
#define BB 4
#define NN 40960
#define KK 16
#define DOUT 16
#define BN_EPS 1e-5f

// Scratch: xyz padded to float4 so each neighbor gather is a single LDG.128.
// B*N = 163840 float4 = 2.62 MB. __device__ global => allocation-free.
__device__ float4 g_xyz4[BB * NN];

// --- Kernel 1: pack xyz [B,N,3] f32 -> float4 scratch, 4 points/thread ----
__global__ void pack_xyz_kernel(const float4* __restrict__ xyz4) {
    int i = blockIdx.x * blockDim.x + threadIdx.x;   // 0 .. B*N/4-1
    if (i < BB * NN / 4) {
        float4 a = xyz4[3 * i + 0];   // x0 y0 z0 x1
        float4 b = xyz4[3 * i + 1];   // y1 z1 x2 y2
        float4 c = xyz4[3 * i + 2];   // z2 x3 y3 z3
        float4* o = g_xyz4 + 4 * i;
        o[0] = make_float4(a.x, a.y, a.z, 0.0f);
        o[1] = make_float4(a.w, b.x, b.y, 0.0f);
        o[2] = make_float4(b.z, b.w, c.x, 0.0f);
        o[3] = make_float4(c.y, c.z, c.w, 0.0f);
    }
}

// --- Kernel 2: fused gather + relative-pos encode + conv1x1 + BN + ReLU ---
// Thread = one (b, n, group of 4 consecutive k) -- the R8 saddle point that
// beat every warps-vs-MLP trade (R7: 40-reg cap spilled; R9/R10: bigger
// threads drowned the L1tex wavefront queue).
// SINGLE change vs R8: (256,5) -> cap 48 regs, 5 CTAs/SM = 40 warps (+25%
// latency hiding at unchanged per-warp MLP=4). 17% reg squeeze should CSE
// away, not spill (live set ~19 floats).
__global__ __launch_bounds__(256, 5) void lse_kernel(
    const int* __restrict__ idx,         // [B,N,K] int32
    const float* __restrict__ W,         // [DOUT,10]
    const float* __restrict__ gamma,
    const float* __restrict__ beta,
    const float* __restrict__ rmean,
    const float* __restrict__ rvar,
    float* __restrict__ out)             // [B,DOUT,N,K]
{
    // Per-block prepped weights: y[o] = bias + w0*dist + A.tile + Bm.neigh
    __shared__ float sW0[DOUT];
    __shared__ float sA[DOUT][3];
    __shared__ float sBm[DOUT][3];
    __shared__ float sBias[DOUT];

    int t = threadIdx.x;
    if (t < DOUT) {
        float inv_std = rsqrtf(rvar[t] + BN_EPS);
        float sc = gamma[t] * inv_std;
        const float* w = W + t * 10;
        sW0[t] = w[0] * sc;
#pragma unroll
        for (int c = 0; c < 3; c++) {
            float wr = w[1 + c], wt = w[4 + c], wn = w[7 + c];
            sA[t][c]  = (wr + wt) * sc;   // coefficient of tile (center xyz)
            sBm[t][c] = (wn - wr) * sc;   // coefficient of neighbor xyz
        }
        sBias[t] = beta[t] - gamma[t] * rmean[t] * inv_std;
    }
    __syncthreads();

    int gid = blockIdx.x * blockDim.x + t;           // 0 .. B*N*K/4-1
    int b = gid / (NN * (KK / 4));                   // exact div, N*(K/4)=163840
    int r = gid - b * (NN * (KK / 4));
    int n = r >> 2;
    int k0 = (r & 3) << 2;                           // 0,4,8,12

    // Load 4 int32 neighbor indices in ONE LDG.128 (16B aligned)
    const int4 iv = *(const int4*)(idx + (b * NN + n) * KK + k0);

    const float4* xb = g_xyz4 + b * NN;
    float4 tile = xb[n];                             // broadcast across k-group

    // Random gathers: one LDG.128 each, working set 640 KB/batch -> L2 hits.
    // Front-batched MLP=4 -- the proven sweet spot.
    float4 nb0 = xb[iv.x];
    float4 nb1 = xb[iv.y];
    float4 nb2 = xb[iv.z];
    float4 nb3 = xb[iv.w];

    float rx0 = tile.x - nb0.x, ry0 = tile.y - nb0.y, rz0 = tile.z - nb0.z;
    float rx1 = tile.x - nb1.x, ry1 = tile.y - nb1.y, rz1 = tile.z - nb1.z;
    float rx2 = tile.x - nb2.x, ry2 = tile.y - nb2.y, rz2 = tile.z - nb2.z;
    float rx3 = tile.x - nb3.x, ry3 = tile.y - nb3.y, rz3 = tile.z - nb3.z;
    float d0 = sqrtf(rx0 * rx0 + ry0 * ry0 + rz0 * rz0);
    float d1 = sqrtf(rx1 * rx1 + ry1 * ry1 + rz1 * rz1);
    float d2 = sqrtf(rx2 * rx2 + ry2 * ry2 + rz2 * rz2);
    float d3 = sqrtf(rx3 * rx3 + ry3 * ry3 + rz3 * rz3);

    // out[((b*16+o)*N + n)*K + k0] ; per-o stride = N*K floats
    float* op = out + (b * DOUT * NN + n) * KK + k0;

#pragma unroll
    for (int o = 0; o < DOUT; o++) {
        float a0 = sA[o][0], a1 = sA[o][1], a2 = sA[o][2];
        float m0 = sBm[o][0], m1 = sBm[o][1], m2 = sBm[o][2];
        float w0 = sW0[o];
        // tile term shared by all 4 k
        float tt = sBias[o] + a0 * tile.x + a1 * tile.y + a2 * tile.z;

        float y0 = tt + w0 * d0 + m0 * nb0.x + m1 * nb0.y + m2 * nb0.z;
        float y1 = tt + w0 * d1 + m0 * nb1.x + m1 * nb1.y + m2 * nb1.z;
        float y2 = tt + w0 * d2 + m0 * nb2.x + m1 * nb2.y + m2 * nb2.z;
        float y3 = tt + w0 * d3 + m0 * nb3.x + m1 * nb3.y + m2 * nb3.z;

        float4 v = make_float4(fmaxf(y0, 0.0f), fmaxf(y1, 0.0f),
                               fmaxf(y2, 0.0f), fmaxf(y3, 0.0f));
        *(float4*)(op + o * (NN * KK)) = v;   // STG.128, warp-contiguous per o
    }
}

extern "C" void kernel_launch(void* const* d_in, const int* in_sizes, int n_in,
                              void* d_out, int out_size) {
    // Bind inputs by element count (robust to metadata ordering).
    const float* xyz = 0;
    const int*   idx = 0;
    const float* W   = 0;
    const float* p16[4] = {0, 0, 0, 0};   // gamma, beta, rmean, rvar in order
    int n16 = 0;

    for (int i = 0; i < n_in; i++) {
        switch (in_sizes[i]) {
            case BB * NN * 3:        xyz = (const float*)d_in[i]; break;   // 491520
            case BB * NN * KK:       idx = (const int*)d_in[i];   break;   // 2621440
            case DOUT * 10:          W   = (const float*)d_in[i]; break;   // 160
            case DOUT:               if (n16 < 4) p16[n16++] = (const float*)d_in[i]; break;
            default: break;           // feature (1310720): unused
        }
    }
    const float* gamma = p16[0];
    const float* beta  = p16[1];
    const float* rmean = p16[2];
    const float* rvar  = p16[3];
    float* out = (float*)d_out;
    (void)out_size;

    const int pack_threads = BB * NN / 4;                 // 40960
    pack_xyz_kernel<<<(pack_threads + 255) / 256, 256>>>((const float4*)xyz);

    const int total = BB * NN * (KK / 4);                 // 655360 threads
    lse_kernel<<<total / 256, 256>>>(idx, W, gamma, beta, rmean, rvar, out);
}

// round 12
// speedup vs baseline: 1.4448x; 1.0672x over previous
#include <cuda_runtime.h>

// Problem constants (fixed by the dataset)
#define BB 4
#define NN 40960
#define KK 16
#define DOUT 16
#define BN_EPS 1e-5f

// Scratch: xyz padded to float4 so each neighbor gather is a single LDG.128.
// B*N = 163840 float4 = 2.62 MB. __device__ global => allocation-free.
__device__ float4 g_xyz4[BB * NN];

// --- Kernel 1: pack xyz [B,N,3] f32 -> float4 scratch, 4 points/thread ----
// 3x LDG.128 in + 4x STG.128 out, fully coalesced. 40960 threads total.
__global__ void pack_xyz_kernel(const float4* __restrict__ xyz4) {
    int i = blockIdx.x * blockDim.x + threadIdx.x;   // 0 .. B*N/4-1
    if (i < BB * NN / 4) {
        float4 a = xyz4[3 * i + 0];   // x0 y0 z0 x1
        float4 b = xyz4[3 * i + 1];   // y1 z1 x2 y2
        float4 c = xyz4[3 * i + 2];   // z2 x3 y3 z3
        float4* o = g_xyz4 + 4 * i;
        o[0] = make_float4(a.x, a.y, a.z, 0.0f);
        o[1] = make_float4(a.w, b.x, b.y, 0.0f);
        o[2] = make_float4(b.z, b.w, c.x, 0.0f);
        o[3] = make_float4(c.y, c.z, c.w, 0.0f);
    }
}

// --- Kernel 2: fused gather + relative-pos encode + conv1x1 + BN + ReLU ---
// Thread = one (b, n, group of 4 consecutive k). Writes 16 float4 (one per o).
// Empirical optimum shape (R6-R11 sweep): natural regs=58, 4 CTAs/SM,
// 32 warps, front-batched MLP=4. Every occupancy/MLP trade regressed:
//   R7  40 regs / 6 CTAs         -> 50.0us (serialized loads)
//   R9  87 regs / 2-unit batch   -> 41.0us (too few warps)
//   R10 80 regs / k8 threads     -> 55.9us (L1tex queue contention)
//   R11 48 regs / 5 CTAs         -> 39.6us (queue contention)
// Plain STG (no __stcs): controlled A/B showed __stcs costs ~1us here
// (R6 lse 36.06 plain vs R8 lse 37.02 with __stcs, identical bodies).
__global__ __launch_bounds__(256) void lse_kernel(
    const int* __restrict__ idx,         // [B,N,K] int32
    const float* __restrict__ W,         // [DOUT,10]
    const float* __restrict__ gamma,
    const float* __restrict__ beta,
    const float* __restrict__ rmean,
    const float* __restrict__ rvar,
    float* __restrict__ out)             // [B,DOUT,N,K]
{
    // Per-block prepped weights: y[o] = bias + w0*dist + A.tile + Bm.neigh
    __shared__ float sW0[DOUT];
    __shared__ float sA[DOUT][3];
    __shared__ float sBm[DOUT][3];
    __shared__ float sBias[DOUT];

    int t = threadIdx.x;
    if (t < DOUT) {
        float inv_std = rsqrtf(rvar[t] + BN_EPS);
        float sc = gamma[t] * inv_std;
        const float* w = W + t * 10;
        sW0[t] = w[0] * sc;
#pragma unroll
        for (int c = 0; c < 3; c++) {
            float wr = w[1 + c], wt = w[4 + c], wn = w[7 + c];
            sA[t][c]  = (wr + wt) * sc;   // coefficient of tile (center xyz)
            sBm[t][c] = (wn - wr) * sc;   // coefficient of neighbor xyz
        }
        sBias[t] = beta[t] - gamma[t] * rmean[t] * inv_std;
    }
    __syncthreads();

    int gid = blockIdx.x * blockDim.x + t;           // 0 .. B*N*K/4-1
    int b = gid / (NN * (KK / 4));                   // exact div, N*(K/4)=163840
    int r = gid - b * (NN * (KK / 4));
    int n = r >> 2;
    int k0 = (r & 3) << 2;                           // 0,4,8,12

    // Load 4 int32 neighbor indices in ONE LDG.128 (16B aligned)
    const int4 iv = *(const int4*)(idx + (b * NN + n) * KK + k0);

    const float4* xb = g_xyz4 + b * NN;
    float4 tile = xb[n];                             // broadcast across k-group

    // Random gathers: one LDG.128 each, working set 640 KB/batch -> L2 hits.
    // Front-batched MLP=4 -- the proven sweet spot.
    float4 nb0 = xb[iv.x];
    float4 nb1 = xb[iv.y];
    float4 nb2 = xb[iv.z];
    float4 nb3 = xb[iv.w];

    float rx0 = tile.x - nb0.x, ry0 = tile.y - nb0.y, rz0 = tile.z - nb0.z;
    float rx1 = tile.x - nb1.x, ry1 = tile.y - nb1.y, rz1 = tile.z - nb1.z;
    float rx2 = tile.x - nb2.x, ry2 = tile.y - nb2.y, rz2 = tile.z - nb2.z;
    float rx3 = tile.x - nb3.x, ry3 = tile.y - nb3.y, rz3 = tile.z - nb3.z;
    float d0 = sqrtf(rx0 * rx0 + ry0 * ry0 + rz0 * rz0);
    float d1 = sqrtf(rx1 * rx1 + ry1 * ry1 + rz1 * rz1);
    float d2 = sqrtf(rx2 * rx2 + ry2 * ry2 + rz2 * rz2);
    float d3 = sqrtf(rx3 * rx3 + ry3 * ry3 + rz3 * rz3);

    // out[((b*16+o)*N + n)*K + k0] ; per-o stride = N*K floats
    float* op = out + (b * DOUT * NN + n) * KK + k0;

#pragma unroll
    for (int o = 0; o < DOUT; o++) {
        float a0 = sA[o][0], a1 = sA[o][1], a2 = sA[o][2];
        float m0 = sBm[o][0], m1 = sBm[o][1], m2 = sBm[o][2];
        float w0 = sW0[o];
        // tile term shared by all 4 k
        float tt = sBias[o] + a0 * tile.x + a1 * tile.y + a2 * tile.z;

        float y0 = tt + w0 * d0 + m0 * nb0.x + m1 * nb0.y + m2 * nb0.z;
        float y1 = tt + w0 * d1 + m0 * nb1.x + m1 * nb1.y + m2 * nb1.z;
        float y2 = tt + w0 * d2 + m0 * nb2.x + m1 * nb2.y + m2 * nb2.z;
        float y3 = tt + w0 * d3 + m0 * nb3.x + m1 * nb3.y + m2 * nb3.z;

        float4 v = make_float4(fmaxf(y0, 0.0f), fmaxf(y1, 0.0f),
                               fmaxf(y2, 0.0f), fmaxf(y3, 0.0f));
        *(float4*)(op + o * (NN * KK)) = v;   // plain STG.128, warp-contiguous
    }
}

extern "C" void kernel_launch(void* const* d_in, const int* in_sizes, int n_in,
                              void* d_out, int out_size) {
    // Bind inputs by element count (robust to metadata ordering).
    const float* xyz = 0;
    const int*   idx = 0;
    const float* W   = 0;
    const float* p16[4] = {0, 0, 0, 0};   // gamma, beta, rmean, rvar in order
    int n16 = 0;

    for (int i = 0; i < n_in; i++) {
        switch (in_sizes[i]) {
            case BB * NN * 3:        xyz = (const float*)d_in[i]; break;   // 491520
            case BB * NN * KK:       idx = (const int*)d_in[i];   break;   // 2621440
            case DOUT * 10:          W   = (const float*)d_in[i]; break;   // 160
            case DOUT:               if (n16 < 4) p16[n16++] = (const float*)d_in[i]; break;
            default: break;           // feature (1310720): unused
        }
    }
    const float* gamma = p16[0];
    const float* beta  = p16[1];
    const float* rmean = p16[2];
    const float* rvar  = p16[3];
    float* out = (float*)d_out;
    (void)out_size;

    const int pack_threads = BB * NN / 4;                 // 40960
    pack_xyz_kernel<<<(pack_threads + 255) / 256, 256>>>((const float4*)xyz);

    const int total = BB * NN * (KK / 4);                 // 655360 threads
    lse_kernel<<<total / 256, 256>>>(idx, W, gamma, beta, rmean, rvar, out);
}

// round 13
// speedup vs baseline: 1.5199x; 1.0520x over previous
#include <cuda_runtime.h>

// Problem constants (fixed by the dataset)
#define BB 4
#define NN 40960
#define KK 16
#define DOUT 16
#define BN_EPS 1e-5f

// Scratch: xyz padded to float4 so each neighbor gather is a single LDG.128.
// B*N = 163840 float4 = 2.62 MB. __device__ global => allocation-free.
__device__ float4 g_xyz4[BB * NN];

// --- Kernel 1: pack xyz [B,N,3] f32 -> float4 scratch, 4 points/thread ----
__global__ void pack_xyz_kernel(const float4* __restrict__ xyz4) {
    int i = blockIdx.x * blockDim.x + threadIdx.x;   // 0 .. B*N/4-1
    if (i < BB * NN / 4) {
        float4 a = xyz4[3 * i + 0];   // x0 y0 z0 x1
        float4 b = xyz4[3 * i + 1];   // y1 z1 x2 y2
        float4 c = xyz4[3 * i + 2];   // z2 x3 y3 z3
        float4* o = g_xyz4 + 4 * i;
        o[0] = make_float4(a.x, a.y, a.z, 0.0f);
        o[1] = make_float4(a.w, b.x, b.y, 0.0f);
        o[2] = make_float4(b.z, b.w, c.x, 0.0f);
        o[3] = make_float4(c.y, c.z, c.w, 0.0f);
    }
}

// --- Kernel 2: fused gather + relative-pos encode + conv1x1 + BN + ReLU ---
// Thread = one (b, n, 4 consecutive k). R8 shape: natural regs=58, 4 CTAs/SM,
// 32 warps, front-batched MLP=4 (every occupancy/MLP trade regressed: R7 cap
// ->50us, R9 2-unit ->41us, R10 k8 ->56us, R11 5CTA ->39.6us).
//
// Cache policy targets the TIMED graph-replay loop, not the single-launch ncu
// profile (measured: __stcs total 35.9us vs plain 41.4us; the 168MB of dirty
// output lines otherwise drain into the next replay's gathers). __stcs on out,
// __ldcs on the once-read 10.5MB idx stream: both evict-first, keeping L2 for
// the hot 2.6MB xyz gather set across replays.
__global__ __launch_bounds__(256) void lse_kernel(
    const int* __restrict__ idx,         // [B,N,K] int32
    const float* __restrict__ W,         // [DOUT,10]
    const float* __restrict__ gamma,
    const float* __restrict__ beta,
    const float* __restrict__ rmean,
    const float* __restrict__ rvar,
    float* __restrict__ out)             // [B,DOUT,N,K]
{
    // Per-block prepped weights: y[o] = bias + w0*dist + A.tile + Bm.neigh
    __shared__ float sW0[DOUT];
    __shared__ float sA[DOUT][3];
    __shared__ float sBm[DOUT][3];
    __shared__ float sBias[DOUT];

    int t = threadIdx.x;
    if (t < DOUT) {
        float inv_std = rsqrtf(rvar[t] + BN_EPS);
        float sc = gamma[t] * inv_std;
        const float* w = W + t * 10;
        sW0[t] = w[0] * sc;
#pragma unroll
        for (int c = 0; c < 3; c++) {
            float wr = w[1 + c], wt = w[4 + c], wn = w[7 + c];
            sA[t][c]  = (wr + wt) * sc;   // coefficient of tile (center xyz)
            sBm[t][c] = (wn - wr) * sc;   // coefficient of neighbor xyz
        }
        sBias[t] = beta[t] - gamma[t] * rmean[t] * inv_std;
    }
    __syncthreads();

    int gid = blockIdx.x * blockDim.x + t;           // 0 .. B*N*K/4-1
    int b = gid / (NN * (KK / 4));                   // exact div, N*(K/4)=163840
    int r = gid - b * (NN * (KK / 4));
    int n = r >> 2;
    int k0 = (r & 3) << 2;                           // 0,4,8,12

    // 4 int32 neighbor indices in ONE LDG.128, streaming (read once/replay)
    const int4 iv = __ldcs((const int4*)(idx + (b * NN + n) * KK + k0));

    const float4* xb = g_xyz4 + b * NN;
    float4 tile = xb[n];                             // broadcast across k-group

    // Random gathers: one LDG.128 each, working set 640 KB/batch -> L2 hits.
    // Front-batched MLP=4 -- the proven sweet spot.
    float4 nb0 = xb[iv.x];
    float4 nb1 = xb[iv.y];
    float4 nb2 = xb[iv.z];
    float4 nb3 = xb[iv.w];

    float rx0 = tile.x - nb0.x, ry0 = tile.y - nb0.y, rz0 = tile.z - nb0.z;
    float rx1 = tile.x - nb1.x, ry1 = tile.y - nb1.y, rz1 = tile.z - nb1.z;
    float rx2 = tile.x - nb2.x, ry2 = tile.y - nb2.y, rz2 = tile.z - nb2.z;
    float rx3 = tile.x - nb3.x, ry3 = tile.y - nb3.y, rz3 = tile.z - nb3.z;
    float d0 = sqrtf(rx0 * rx0 + ry0 * ry0 + rz0 * rz0);
    float d1 = sqrtf(rx1 * rx1 + ry1 * ry1 + rz1 * rz1);
    float d2 = sqrtf(rx2 * rx2 + ry2 * ry2 + rz2 * rz2);
    float d3 = sqrtf(rx3 * rx3 + ry3 * ry3 + rz3 * rz3);

    // out[((b*16+o)*N + n)*K + k0] ; per-o stride = N*K floats
    float* op = out + (b * DOUT * NN + n) * KK + k0;

#pragma unroll
    for (int o = 0; o < DOUT; o++) {
        float a0 = sA[o][0], a1 = sA[o][1], a2 = sA[o][2];
        float m0 = sBm[o][0], m1 = sBm[o][1], m2 = sBm[o][2];
        float w0 = sW0[o];
        // tile term shared by all 4 k
        float tt = sBias[o] + a0 * tile.x + a1 * tile.y + a2 * tile.z;

        float y0 = tt + w0 * d0 + m0 * nb0.x + m1 * nb0.y + m2 * nb0.z;
        float y1 = tt + w0 * d1 + m0 * nb1.x + m1 * nb1.y + m2 * nb1.z;
        float y2 = tt + w0 * d2 + m0 * nb2.x + m1 * nb2.y + m2 * nb2.z;
        float y3 = tt + w0 * d3 + m0 * nb3.x + m1 * nb3.y + m2 * nb3.z;

        float4 v = make_float4(fmaxf(y0, 0.0f), fmaxf(y1, 0.0f),
                               fmaxf(y2, 0.0f), fmaxf(y3, 0.0f));
        // Streaming store: evict-first keeps L2 clean across graph replays
        // (timed A/B: 35.9us with __stcs vs 41.4us plain, twice reproduced).
        __stcs((float4*)(op + o * (NN * KK)), v);
    }
}

extern "C" void kernel_launch(void* const* d_in, const int* in_sizes, int n_in,
                              void* d_out, int out_size) {
    // Bind inputs by element count (robust to metadata ordering).
    const float* xyz = 0;
    const int*   idx = 0;
    const float* W   = 0;
    const float* p16[4] = {0, 0, 0, 0};   // gamma, beta, rmean, rvar in order
    int n16 = 0;

    for (int i = 0; i < n_in; i++) {
        switch (in_sizes[i]) {
            case BB * NN * 3:        xyz = (const float*)d_in[i]; break;   // 491520
            case BB * NN * KK:       idx = (const int*)d_in[i];   break;   // 2621440
            case DOUT * 10:          W   = (const float*)d_in[i]; break;   // 160
            case DOUT:               if (n16 < 4) p16[n16++] = (const float*)d_in[i]; break;
            default: break;           // feature (1310720): unused
        }
    }
    const float* gamma = p16[0];
    const float* beta  = p16[1];
    const float* rmean = p16[2];
    const float* rvar  = p16[3];
    float* out = (float*)d_out;
    (void)out_size;

    const int pack_threads = BB * NN / 4;                 // 40960
    pack_xyz_kernel<<<(pack_threads + 255) / 256, 256>>>((const float4*)xyz);

    const int total = BB * NN * (KK / 4);                 // 655360 threads
    lse_kernel<<<total / 256, 256>>>(idx, W, gamma, beta, rmean, rvar, out);
}